// round 2
// baseline (speedup 1.0000x reference)
#include <cuda_runtime.h>
#include <cuda_bf16.h>

#define BN    32
#define LN    36864
#define CN    16
#define KN    24
#define LOUT  1536
#define DN    512
#define CKN   384      // C*K
#define TM    32       // rows (lout) per CTA
#define KC    8        // k-chunk for GEMM B staging
#define NTHR  256
#define VPAD  36       // padded TM for s_val rows (multiple of 4 for float4 align)

// smem layout (floats):
//  s_xt  : [CN][TM*KN]      = 16*768  = 12288
//  s_val : [CKN][VPAD]      = 384*36  = 13824
//  s_off : [TM][48]         = 1536
//  s_b   : [KC][DN]         = 8*512   = 4096
#define SM_XT   0
#define SM_VAL  (SM_XT + CN * (TM * KN))
#define SM_OFF  (SM_VAL + CKN * VPAD)
#define SM_B    (SM_OFF + TM * 48)
#define SM_TOT  (SM_B + KC * DN)          // 31744 floats = 126976 bytes

__global__ __launch_bounds__(NTHR, 1)
void deform_fused_kernel(const float* __restrict__ x,
                         const float* __restrict__ w_off,
                         const float* __restrict__ b_off,
                         const float* __restrict__ w_def,
                         const float* __restrict__ b_def,
                         float* __restrict__ out)
{
    extern __shared__ float smem[];
    float* s_xt  = smem + SM_XT;
    float* s_val = smem + SM_VAL;
    float* s_off = smem + SM_OFF;
    float* s_b   = smem + SM_B;

    const int t = threadIdx.x;
    const int g = blockIdx.x;
    const int b = g / (LOUT / TM);
    const int lout0 = (g % (LOUT / TM)) * TM;

    const float* xb = x + (size_t)b * LN * CN;
    const int base_i = lout0 * KN;             // window start row in L

    // ---------------- Phase 1: load x window, store transposed [c][i] ----------
    {
        const float4* xw4 = (const float4*)(xb + (size_t)base_i * CN);
        #pragma unroll
        for (int it = 0; it < (TM * KN * CN / 4) / NTHR; it++) {
            int idx = t + it * NTHR;            // 0 .. 3071
            float4 v = __ldg(&xw4[idx]);
            int i  = idx >> 2;                  // L-row within window (0..767)
            int c4 = (idx & 3) * 4;
            s_xt[(c4 + 0) * (TM * KN) + i] = v.x;
            s_xt[(c4 + 1) * (TM * KN) + i] = v.y;
            s_xt[(c4 + 2) * (TM * KN) + i] = v.z;
            s_xt[(c4 + 3) * (TM * KN) + i] = v.w;
        }
    }
    __syncthreads();

    // ---------------- Phase 2: offset conv  off[m][o] ---------------------------
    // off[m][o] = b_off[o] + sum_{c,k} xwin[m*K+k][c] * w_off[o,c,k]
    #pragma unroll
    for (int it = 0; it < (TM * 48) / NTHR; it++) {
        int j = t + it * NTHR;                  // 0 .. 1535
        int m = j / 48;
        int o = j % 48;
        const float4* wo4 = (const float4*)(w_off + o * CKN);
        float acc = __ldg(&b_off[o]);
        #pragma unroll
        for (int c = 0; c < CN; c++) {
            const float4* xr = (const float4*)(s_xt + c * (TM * KN) + m * KN);
            #pragma unroll
            for (int q = 0; q < KN / 4; q++) {
                float4 wv = __ldg(&wo4[c * (KN / 4) + q]);
                float4 xv = xr[q];
                acc += xv.x * wv.x + xv.y * wv.y + xv.z * wv.z + xv.w * wv.w;
            }
        }
        s_off[j] = acc;
    }
    __syncthreads();

    // ---------------- Phase 3: bilinear sampling -> s_val[ck][m] ----------------
    #pragma unroll
    for (int it = 0; it < (TM * KN) / NTHR; it++) {
        int j = t + it * NTHR;                  // 0 .. 767
        int m = j / KN;
        int k = j % KN;
        float dy = s_off[m * 48 + 2 * k];
        float dx = s_off[m * 48 + 2 * k + 1];
        float wy = fmaxf(0.0f, 1.0f - fabsf(dy));
        int lout = lout0 + m;
        float px = (float)(lout * KN + k) + dx;
        bool valid = (px > -1.0f) && (px < (float)LN);
        float x0f = floorf(px);
        float lw = px - x0f;
        int i0 = (int)x0f;
        int i1 = i0 + 1;
        float w0 = (valid && i0 >= 0 && i0 < LN) ? (1.0f - lw) * wy : 0.0f;
        float w1 = (valid && i1 >= 0 && i1 < LN) ? lw * wy : 0.0f;
        int i0c = min(max(i0, 0), LN - 1);
        int i1c = min(max(i1, 0), LN - 1);
        const float4* p0 = (const float4*)(xb + (size_t)i0c * CN);
        const float4* p1 = (const float4*)(xb + (size_t)i1c * CN);
        #pragma unroll
        for (int q = 0; q < 4; q++) {
            float4 v0 = __ldg(&p0[q]);
            float4 v1 = __ldg(&p1[q]);
            int c = q * 4;
            s_val[((c + 0) * KN + k) * VPAD + m] = v0.x * w0 + v1.x * w1;
            s_val[((c + 1) * KN + k) * VPAD + m] = v0.y * w0 + v1.y * w1;
            s_val[((c + 2) * KN + k) * VPAD + m] = v0.z * w0 + v1.z * w1;
            s_val[((c + 3) * KN + k) * VPAD + m] = v0.w * w0 + v1.w * w1;
        }
    }
    __syncthreads();

    // ---------------- Phase 4: GEMM  out[m][d] = val[m][ck] * w_def[d][ck] ------
    const int r0 = (t / 64) * 8;                // 4 row blocks * 8 = 32 rows
    const int c0 = (t % 64) * 8;                // 64 col blocks * 8 = 512 cols

    float acc[8][8];
    #pragma unroll
    for (int i = 0; i < 8; i++)
        #pragma unroll
        for (int jj = 0; jj < 8; jj++) acc[i][jj] = 0.0f;

    for (int ck0 = 0; ck0 < CKN; ck0 += KC) {
        // stage B chunk: s_b[kk][d] = w_def[d][ck0+kk]
        #pragma unroll
        for (int h = 0; h < 2; h++) {
            int d = t + h * NTHR;
            const float4* wd4 = (const float4*)(w_def + (size_t)d * CKN + ck0);
            float4 u0 = __ldg(&wd4[0]);
            float4 u1 = __ldg(&wd4[1]);
            s_b[0 * DN + d] = u0.x;  s_b[1 * DN + d] = u0.y;
            s_b[2 * DN + d] = u0.z;  s_b[3 * DN + d] = u0.w;
            s_b[4 * DN + d] = u1.x;  s_b[5 * DN + d] = u1.y;
            s_b[6 * DN + d] = u1.z;  s_b[7 * DN + d] = u1.w;
        }
        __syncthreads();
        #pragma unroll
        for (int kk = 0; kk < KC; kk++) {
            float4 a0 = *(const float4*)(s_val + (ck0 + kk) * VPAD + r0);
            float4 a1 = *(const float4*)(s_val + (ck0 + kk) * VPAD + r0 + 4);
            float4 b0 = *(const float4*)(s_b + kk * DN + c0);
            float4 b1 = *(const float4*)(s_b + kk * DN + c0 + 4);
            float av[8] = {a0.x, a0.y, a0.z, a0.w, a1.x, a1.y, a1.z, a1.w};
            float bv[8] = {b0.x, b0.y, b0.z, b0.w, b1.x, b1.y, b1.z, b1.w};
            #pragma unroll
            for (int i = 0; i < 8; i++)
                #pragma unroll
                for (int jj = 0; jj < 8; jj++)
                    acc[i][jj] += av[i] * bv[jj];
        }
        __syncthreads();
    }

    // ---------------- Epilogue: bias + store ------------------------------------
    float bias[8];
    #pragma unroll
    for (int jj = 0; jj < 8; jj++) bias[jj] = __ldg(&b_def[c0 + jj]);

    #pragma unroll
    for (int i = 0; i < 8; i++) {
        size_t row = (size_t)b * LOUT + (lout0 + r0 + i);
        float* orow = out + row * DN + c0;
        float4 o0, o1;
        o0.x = acc[i][0] + bias[0];  o0.y = acc[i][1] + bias[1];
        o0.z = acc[i][2] + bias[2];  o0.w = acc[i][3] + bias[3];
        o1.x = acc[i][4] + bias[4];  o1.y = acc[i][5] + bias[5];
        o1.z = acc[i][6] + bias[6];  o1.w = acc[i][7] + bias[7];
        *(float4*)(orow + 0) = o0;
        *(float4*)(orow + 4) = o1;
    }
}

extern "C" void kernel_launch(void* const* d_in, const int* in_sizes, int n_in,
                              void* d_out, int out_size)
{
    const float* x     = (const float*)d_in[0];
    const float* w_off = (const float*)d_in[1];
    const float* b_off = (const float*)d_in[2];
    const float* w_def = (const float*)d_in[3];
    const float* b_def = (const float*)d_in[4];
    float* out = (float*)d_out;

    const int smem_bytes = SM_TOT * (int)sizeof(float);   // 126976 B
    static bool attr_set = false;   // idempotent host-side attribute (not a guard on work)
    if (!attr_set) {
        cudaFuncSetAttribute(deform_fused_kernel,
                             cudaFuncAttributeMaxDynamicSharedMemorySize, smem_bytes);
        attr_set = true;
    }

    dim3 grid(BN * (LOUT / TM));   // 1536 CTAs
    dim3 block(NTHR);
    deform_fused_kernel<<<grid, block, smem_bytes>>>(x, w_off, b_off, w_def, b_def, out);
}